// round 7
// baseline (speedup 1.0000x reference)
#include <cuda_runtime.h>
#include <cuda_fp16.h>
#include <cstdint>

// Problem dims
#define NB   2048
#define ND   512
#define NH   64
#define NHID 2048

// Tiling
#define BM   64
#define BN   128
#define BK   64
#define NTHREADS 256
#define NCHUNK 128           // 16 n-tiles * 8 k-tiles

// smem layout (bytes). A: 64 rows x 1024B, XOR swizzle (no pad) = 65536.
// B: 3 stages x (64 rows x 256B) XOR swizzle = 49152.
#define OFF_A  0
#define ASZ    65536
#define OFF_B  ASZ
#define BSTG   16384
#define NSTAGE 3
#define OFF_ROWACC (OFF_B + NSTAGE * BSTG)   // 114688
#define SMEM_DYN   (OFF_ROWACC + BM * 4)     // 114944 (2 CTAs/SM fit)

// fp16 copies + packed epilogue params (device globals; allocation-free)
__device__ __half g_Wh[(size_t)NH * ND * NHID];   // [H][D][HID], n contiguous
__device__ __half g_Xh[(size_t)NB * ND];          // [B][D], k contiguous
__device__ float4 g_pk4[(size_t)NH * (NHID / 2)]; // (b1[2c],b1[2c+1],W2[2c],W2[2c+1])

__device__ __forceinline__ uint32_t smem_u32(const void* p) {
    return (uint32_t)__cvta_generic_to_shared(p);
}
__device__ __forceinline__ void cp16(uint32_t dst, const void* src) {
    asm volatile("cp.async.cg.shared.global [%0], [%1], 16;" :: "r"(dst), "l"(src));
}
__device__ __forceinline__ void cp_commit() {
    asm volatile("cp.async.commit_group;" ::: "memory");
}
__device__ __forceinline__ float lrelu(float v) {
    return (v >= 0.f) ? v : 0.01f * v;
}

// ---------------------------------------------------------------------------
// Converts
// ---------------------------------------------------------------------------
__global__ void convert_w_kernel(const float* __restrict__ W1) {
    size_t i = (size_t)blockIdx.x * blockDim.x + threadIdx.x;
    const size_t n4 = (size_t)NH * ND * NHID / 4;
    if (i >= n4) return;
    float4 v = ((const float4*)W1)[i];
    __half2* d = (__half2*)g_Wh;
    d[2 * i]     = __floats2half2_rn(v.x, v.y);
    d[2 * i + 1] = __floats2half2_rn(v.z, v.w);
}
__global__ void convert_x_kernel(const float* __restrict__ X) {
    size_t i = (size_t)blockIdx.x * blockDim.x + threadIdx.x;
    const size_t n4 = (size_t)NB * ND / 4;
    if (i >= n4) return;
    float4 v = ((const float4*)X)[i];
    __half2* d = (__half2*)g_Xh;
    d[2 * i]     = __floats2half2_rn(v.x, v.y);
    d[2 * i + 1] = __floats2half2_rn(v.z, v.w);
}
__global__ void pack_kernel(const float* __restrict__ b1, const float* __restrict__ W2) {
    int i = blockIdx.x * blockDim.x + threadIdx.x;     // 64 * 1024
    if (i >= NH * (NHID / 2)) return;
    int h = i >> 10, c = i & 1023;
    const float* b = b1 + (size_t)h * NHID + 2 * c;
    const float* w = W2 + (size_t)h * NHID + 2 * c;
    g_pk4[i] = make_float4(b[0], b[1], w[0], w[1]);
}

// ---------------------------------------------------------------------------
// Main fused kernel. CTA = (64-row m-tile, head); 2 CTAs/SM so one CTA's MMA
// hides the other's barriers/staging/epilogue. A resident (XOR swizzle);
// B streamed via 3-stage cp.async pipeline. 8 warps in 2(M)x4(N), tile 32x32.
// ---------------------------------------------------------------------------
__global__ void __launch_bounds__(NTHREADS, 2)
mhmlp_main_kernel(const float* __restrict__ b2, float* __restrict__ out)
{
    extern __shared__ char smem[];
    const uint32_t sbase = smem_u32(smem);
    float* rowacc = (float*)(smem + OFF_ROWACC);

    const int tid  = threadIdx.x;
    const int lane = tid & 31;
    const int wid  = tid >> 5;
    const int wm   = wid >> 2;      // 0..1 : 32-row band
    const int wn   = wid & 3;       // 0..3 : 32-col band

    const int mt = blockIdx.x;      // 32 (fast dim -> head weights hot in L2)
    const int h  = blockIdx.y;      // 64
    const int m0 = mt * BM;

    if (tid < BM) rowacc[tid] = 0.f;

    const __half* __restrict__ Wh_h = g_Wh + (size_t)h * ND * NHID;
    const float4* __restrict__ pk_h = g_pk4 + (size_t)h * (NHID / 2);

    // ---- prologue: stage ALL of A (committed with B chunk 0) ----
    #pragma unroll
    for (int i = 0; i < 16; i++) {               // 4096 segs of 16B
        int t = tid + i * NTHREADS;
        int r = t >> 6, s = t & 63;              // row r (1024B), seg s
        const void* src = g_Xh + (size_t)(m0 + r) * ND + s * 8;
        uint32_t off = (uint32_t)(r * 1024 + s * 16);
        cp16(sbase + OFF_A + (off ^ ((uint32_t)(r & 7) << 4)), src);
    }

    auto stageB = [&](int cc) {
        const int nt = cc >> 3, kt = cc & 7, buf = cc % NSTAGE;
        #pragma unroll
        for (int i = 0; i < 4; i++) {            // 1024 segs of 16B
            int t = tid + i * NTHREADS;
            int r = t >> 4, s = t & 15;          // k-row r (256B), seg s
            const void* src = Wh_h + (size_t)(kt * BK + r) * NHID + nt * BN + s * 8;
            uint32_t off = (uint32_t)(r * 256 + s * 16);
            cp16(sbase + OFF_B + buf * BSTG + (off ^ ((uint32_t)(r & 7) << 4)), src);
        }
        cp_commit();
    };

    stageB(0);          // group 0: A + B0
    stageB(1);          // group 1: B1

    float c[2][4][4];
    #pragma unroll
    for (int mi = 0; mi < 2; mi++)
        #pragma unroll
        for (int ni = 0; ni < 4; ni++)
            #pragma unroll
            for (int e = 0; e < 4; e++) c[mi][ni][e] = 0.f;
    float accrow[4] = {0.f, 0.f, 0.f, 0.f};

    for (int cc = 0; cc < NCHUNK; ++cc) {
        if (cc + 2 < NCHUNK) stageB(cc + 2); else cp_commit();
        asm volatile("cp.async.wait_group 2;" ::: "memory");
        __syncthreads();      // chunk cc data visible

        const int kt = cc & 7;
        const uint32_t bB = sbase + OFF_B + (cc % NSTAGE) * BSTG;

        #pragma unroll
        for (int ks = 0; ks < 4; ks++) {
            uint32_t a[2][4];
            #pragma unroll
            for (int mi = 0; mi < 2; mi++) {
                int row = wm * 32 + mi * 16 + (lane & 15);
                uint32_t off = (uint32_t)(row * 1024
                             + (kt * BK + ks * 16 + (lane >> 4) * 8) * 2);
                uint32_t ad = sbase + OFF_A + (off ^ ((uint32_t)(row & 7) << 4));
                asm volatile(
                    "ldmatrix.sync.aligned.m8n8.x4.shared.b16 {%0,%1,%2,%3}, [%4];"
                    : "=r"(a[mi][0]), "=r"(a[mi][1]), "=r"(a[mi][2]), "=r"(a[mi][3])
                    : "r"(ad));
            }
            uint32_t bf[4][2];
            #pragma unroll
            for (int np = 0; np < 2; np++) {
                int r = ks * 16 + (lane & 15);
                int n0 = wn * 32 + np * 16 + (lane >> 4) * 8;
                uint32_t off = (uint32_t)(r * 256 + n0 * 2);
                uint32_t ad = bB + (off ^ ((uint32_t)(r & 7) << 4));
                uint32_t r0, r1, r2, r3;
                asm volatile(
                    "ldmatrix.sync.aligned.m8n8.x4.trans.shared.b16 {%0,%1,%2,%3}, [%4];"
                    : "=r"(r0), "=r"(r1), "=r"(r2), "=r"(r3) : "r"(ad));
                bf[2 * np][0] = r0;     bf[2 * np][1] = r1;
                bf[2 * np + 1][0] = r2; bf[2 * np + 1][1] = r3;
            }
            #pragma unroll
            for (int mi = 0; mi < 2; mi++)
                #pragma unroll
                for (int ni = 0; ni < 4; ni++) {
                    asm volatile(
                        "mma.sync.aligned.m16n8k16.row.col.f32.f16.f16.f32 "
                        "{%0,%1,%2,%3}, {%4,%5,%6,%7}, {%8,%9}, {%0,%1,%2,%3};"
                        : "+f"(c[mi][ni][0]), "+f"(c[mi][ni][1]),
                          "+f"(c[mi][ni][2]), "+f"(c[mi][ni][3])
                        : "r"(a[mi][0]), "r"(a[mi][1]), "r"(a[mi][2]), "r"(a[mi][3]),
                          "r"(bf[ni][0]), "r"(bf[ni][1]));
                }
        }
        __syncthreads();      // reads of buffer cc done before restage

        if ((cc & 7) == 7) {    // K complete -> fused epilogue for n-tile
            const int nt = cc >> 3;
            #pragma unroll
            for (int ni = 0; ni < 4; ni++) {
                int cidx = nt * (BN / 2) + wn * 16 + ni * 4 + (lane & 3);
                float4 pk = __ldg(&pk_h[cidx]);
                #pragma unroll
                for (int mi = 0; mi < 2; mi++)
                    #pragma unroll
                    for (int e = 0; e < 4; e++) {
                        float bia = (e & 1) ? pk.y : pk.x;
                        float w2v = (e & 1) ? pk.w : pk.z;
                        float p = c[mi][ni][e] + bia;
                        accrow[mi * 2 + (e >> 1)] =
                            fmaf(lrelu(p), w2v, accrow[mi * 2 + (e >> 1)]);
                        c[mi][ni][e] = 0.f;
                    }
            }
        }
    }

    // reduce 4 lanes sharing each row, then across wn warps via smem atomics
    #pragma unroll
    for (int off = 1; off <= 2; off <<= 1)
        #pragma unroll
        for (int j = 0; j < 4; j++)
            accrow[j] += __shfl_xor_sync(0xffffffffu, accrow[j], off);

    if ((lane & 3) == 0) {
        #pragma unroll
        for (int mi = 0; mi < 2; mi++)
            #pragma unroll
            for (int e2 = 0; e2 < 2; e2++) {
                int row = wm * 32 + mi * 16 + e2 * 8 + (lane >> 2);
                atomicAdd(&rowacc[row], accrow[mi * 2 + e2]);
            }
    }
    __syncthreads();
    if (tid < BM) {
        float v = rowacc[tid] + __ldg(&b2[h]);
        out[(size_t)(m0 + tid) * NH + h] = lrelu(v);
    }
}

// ---------------------------------------------------------------------------
extern "C" void kernel_launch(void* const* d_in, const int* in_sizes, int n_in,
                              void* d_out, int out_size) {
    const float* x  = (const float*)d_in[0];   // [2048, 512]
    const float* W1 = (const float*)d_in[1];   // [64, 512, 2048]
    const float* b1 = (const float*)d_in[2];   // [64, 2048]
    const float* W2 = (const float*)d_in[3];   // [64, 2048]
    const float* b2 = (const float*)d_in[4];   // [64]
    float* out = (float*)d_out;                // [2048, 64]
    (void)in_sizes; (void)n_in; (void)out_size;

    cudaFuncSetAttribute(mhmlp_main_kernel,
                         cudaFuncAttributeMaxDynamicSharedMemorySize, SMEM_DYN);

    {
        size_t n4 = (size_t)NH * ND * NHID / 4;
        convert_w_kernel<<<(int)((n4 + 255) / 256), 256>>>(W1);
    }
    {
        size_t n4 = (size_t)NB * ND / 4;
        convert_x_kernel<<<(int)((n4 + 255) / 256), 256>>>(x);
    }
    {
        int n = NH * (NHID / 2);
        pack_kernel<<<(n + 255) / 256, 256>>>(b1, W2);
    }

    dim3 grid(NB / BM, NH);
    mhmlp_main_kernel<<<grid, NTHREADS, SMEM_DYN>>>(b2, out);
}

// round 8
// speedup vs baseline: 1.0415x; 1.0415x over previous
#include <cuda_runtime.h>
#include <cuda_fp16.h>
#include <cstdint>

// Problem dims
#define NB   2048
#define ND   512
#define NH   64
#define NHID 2048

// Tiling
#define BM   128
#define BN   256
#define BK   64
#define NTHREADS 256
#define NCHUNK 64            // 8 n-tiles * 8 k-tiles

// smem layout (bytes). A resident: 128 rows x 1024B, XOR swizzle = 131072.
// B: 2 stages x (64 k-rows x 512B) XOR swizzle = 65536.
#define OFF_A  0
#define ASZ    131072
#define OFF_B  ASZ
#define BSTG   32768
#define NSTAGE 2
#define OFF_ROWACC (OFF_B + NSTAGE * BSTG)   // 196608
#define SMEM_DYN   (OFF_ROWACC + BM * 4)     // 197120

// fp16 copies + packed epilogue params (device globals; allocation-free)
__device__ __half g_Wh[(size_t)NH * ND * NHID];   // [H][D][HID], n contiguous
__device__ __half g_Xh[(size_t)NB * ND];          // [B][D], k contiguous
__device__ float4 g_pk4[(size_t)NH * (NHID / 2)]; // (b1[2c],b1[2c+1],W2[2c],W2[2c+1])

__device__ __forceinline__ uint32_t smem_u32(const void* p) {
    return (uint32_t)__cvta_generic_to_shared(p);
}
__device__ __forceinline__ void cp16(uint32_t dst, const void* src) {
    asm volatile("cp.async.cg.shared.global [%0], [%1], 16;" :: "r"(dst), "l"(src));
}
__device__ __forceinline__ void cp_commit() {
    asm volatile("cp.async.commit_group;" ::: "memory");
}
__device__ __forceinline__ float lrelu(float v) {
    return (v >= 0.f) ? v : 0.01f * v;
}

// ---------------------------------------------------------------------------
// Converts
// ---------------------------------------------------------------------------
__global__ void convert_w_kernel(const float* __restrict__ W1) {
    size_t i = (size_t)blockIdx.x * blockDim.x + threadIdx.x;
    const size_t n4 = (size_t)NH * ND * NHID / 4;
    if (i >= n4) return;
    float4 v = ((const float4*)W1)[i];
    __half2* d = (__half2*)g_Wh;
    d[2 * i]     = __floats2half2_rn(v.x, v.y);
    d[2 * i + 1] = __floats2half2_rn(v.z, v.w);
}
__global__ void convert_x_kernel(const float* __restrict__ X) {
    size_t i = (size_t)blockIdx.x * blockDim.x + threadIdx.x;
    const size_t n4 = (size_t)NB * ND / 4;
    if (i >= n4) return;
    float4 v = ((const float4*)X)[i];
    __half2* d = (__half2*)g_Xh;
    d[2 * i]     = __floats2half2_rn(v.x, v.y);
    d[2 * i + 1] = __floats2half2_rn(v.z, v.w);
}
__global__ void pack_kernel(const float* __restrict__ b1, const float* __restrict__ W2) {
    int i = blockIdx.x * blockDim.x + threadIdx.x;     // 64 * 1024
    if (i >= NH * (NHID / 2)) return;
    int h = i >> 10, c = i & 1023;
    const float* b = b1 + (size_t)h * NHID + 2 * c;
    const float* w = W2 + (size_t)h * NHID + 2 * c;
    g_pk4[i] = make_float4(b[0], b[1], w[0], w[1]);
}

// ---------------------------------------------------------------------------
// Main fused kernel. CTA = (128-row m-tile, head). 8 warps in 2(M)x4(N),
// warp tile 64x64 -> crossbar traffic halved vs 4x4 grid. A resident;
// B double-buffered cp.async. Fused epilogue per n-tile.
// ---------------------------------------------------------------------------
__global__ void __launch_bounds__(NTHREADS, 1)
mhmlp_main_kernel(const float* __restrict__ b2, float* __restrict__ out)
{
    extern __shared__ char smem[];
    const uint32_t sbase = smem_u32(smem);
    float* rowacc = (float*)(smem + OFF_ROWACC);

    const int tid  = threadIdx.x;
    const int lane = tid & 31;
    const int wid  = tid >> 5;
    const int wm   = wid >> 2;      // 0..1 : 64-row band
    const int wn   = wid & 3;       // 0..3 : 64-col band

    const int mt = blockIdx.x;      // 16 (fast dim -> head weights hot in L2)
    const int h  = blockIdx.y;      // 64
    const int m0 = mt * BM;

    if (tid < BM) rowacc[tid] = 0.f;

    const __half* __restrict__ Wh_h = g_Wh + (size_t)h * ND * NHID;
    const float4* __restrict__ pk_h = g_pk4 + (size_t)h * (NHID / 2);

    // ---- prologue: stage ALL of A (committed with B chunk 0) ----
    #pragma unroll
    for (int i = 0; i < 32; i++) {               // 8192 segs of 16B
        int t = tid + i * NTHREADS;
        int r = t >> 6, s = t & 63;              // row r (1024B), seg s
        const void* src = g_Xh + (size_t)(m0 + r) * ND + s * 8;
        uint32_t off = (uint32_t)(r * 1024 + s * 16);
        cp16(sbase + OFF_A + (off ^ ((uint32_t)(r & 7) << 4)), src);
    }

    auto stageB = [&](int cc) {
        const int nt = cc >> 3, kt = cc & 7, buf = cc & 1;
        #pragma unroll
        for (int i = 0; i < 8; i++) {            // 2048 segs of 16B
            int t = tid + i * NTHREADS;
            int r = t >> 5, s = t & 31;          // k-row r (512B), seg s
            const void* src = Wh_h + (size_t)(kt * BK + r) * NHID + nt * BN + s * 8;
            uint32_t off = (uint32_t)(r * 512 + s * 16);
            cp16(sbase + OFF_B + buf * BSTG + (off ^ ((uint32_t)(r & 7) << 4)), src);
        }
        cp_commit();
    };

    stageB(0);          // group 0: A + B0

    float c[4][8][4];
    #pragma unroll
    for (int mi = 0; mi < 4; mi++)
        #pragma unroll
        for (int ni = 0; ni < 8; ni++)
            #pragma unroll
            for (int e = 0; e < 4; e++) c[mi][ni][e] = 0.f;
    float accrow[8] = {0.f,0.f,0.f,0.f,0.f,0.f,0.f,0.f};

    for (int cc = 0; cc < NCHUNK; ++cc) {
        if (cc + 1 < NCHUNK) stageB(cc + 1); else cp_commit();
        asm volatile("cp.async.wait_group 1;" ::: "memory");
        __syncthreads();      // chunk cc data visible

        const int kt = cc & 7;
        const uint32_t bB = sbase + OFF_B + (cc & 1) * BSTG;

        #pragma unroll
        for (int ks = 0; ks < 4; ks++) {
            uint32_t a[4][4];
            #pragma unroll
            for (int mi = 0; mi < 4; mi++) {
                int row = wm * 64 + mi * 16 + (lane & 15);
                uint32_t off = (uint32_t)(row * 1024
                             + (kt * BK + ks * 16 + (lane >> 4) * 8) * 2);
                uint32_t ad = sbase + OFF_A + (off ^ ((uint32_t)(row & 7) << 4));
                asm volatile(
                    "ldmatrix.sync.aligned.m8n8.x4.shared.b16 {%0,%1,%2,%3}, [%4];"
                    : "=r"(a[mi][0]), "=r"(a[mi][1]), "=r"(a[mi][2]), "=r"(a[mi][3])
                    : "r"(ad));
            }
            uint32_t bf[8][2];
            #pragma unroll
            for (int np = 0; np < 4; np++) {
                int r = ks * 16 + (lane & 15);
                int n0 = wn * 64 + np * 16 + (lane >> 4) * 8;
                uint32_t off = (uint32_t)(r * 512 + n0 * 2);
                uint32_t ad = bB + (off ^ ((uint32_t)(r & 7) << 4));
                uint32_t r0, r1, r2, r3;
                asm volatile(
                    "ldmatrix.sync.aligned.m8n8.x4.trans.shared.b16 {%0,%1,%2,%3}, [%4];"
                    : "=r"(r0), "=r"(r1), "=r"(r2), "=r"(r3) : "r"(ad));
                bf[2 * np][0] = r0;     bf[2 * np][1] = r1;
                bf[2 * np + 1][0] = r2; bf[2 * np + 1][1] = r3;
            }
            #pragma unroll
            for (int mi = 0; mi < 4; mi++)
                #pragma unroll
                for (int ni = 0; ni < 8; ni++) {
                    asm volatile(
                        "mma.sync.aligned.m16n8k16.row.col.f32.f16.f16.f32 "
                        "{%0,%1,%2,%3}, {%4,%5,%6,%7}, {%8,%9}, {%0,%1,%2,%3};"
                        : "+f"(c[mi][ni][0]), "+f"(c[mi][ni][1]),
                          "+f"(c[mi][ni][2]), "+f"(c[mi][ni][3])
                        : "r"(a[mi][0]), "r"(a[mi][1]), "r"(a[mi][2]), "r"(a[mi][3]),
                          "r"(bf[ni][0]), "r"(bf[ni][1]));
                }
        }
        __syncthreads();      // reads of buffer cc done before it is restaged

        if ((cc & 7) == 7) {    // K complete -> fused epilogue for this n-tile
            const int nt = cc >> 3;
            #pragma unroll
            for (int ni = 0; ni < 8; ni++) {
                int cidx = nt * (BN / 2) + wn * 32 + ni * 4 + (lane & 3);
                float4 pk = __ldg(&pk_h[cidx]);
                #pragma unroll
                for (int mi = 0; mi < 4; mi++)
                    #pragma unroll
                    for (int e = 0; e < 4; e++) {
                        float bia = (e & 1) ? pk.y : pk.x;
                        float w2v = (e & 1) ? pk.w : pk.z;
                        float p = c[mi][ni][e] + bia;
                        accrow[mi * 2 + (e >> 1)] =
                            fmaf(lrelu(p), w2v, accrow[mi * 2 + (e >> 1)]);
                        c[mi][ni][e] = 0.f;
                    }
            }
        }
    }

    // reduce 4 lanes sharing each row, then across wn warps via smem atomics
    #pragma unroll
    for (int off = 1; off <= 2; off <<= 1)
        #pragma unroll
        for (int j = 0; j < 8; j++)
            accrow[j] += __shfl_xor_sync(0xffffffffu, accrow[j], off);

    if ((lane & 3) == 0) {
        #pragma unroll
        for (int mi = 0; mi < 4; mi++)
            #pragma unroll
            for (int e2 = 0; e2 < 2; e2++) {
                int row = wm * 64 + mi * 16 + e2 * 8 + (lane >> 2);
                atomicAdd(&rowacc[row], accrow[mi * 2 + e2]);
            }
    }
    __syncthreads();
    if (tid < BM) {
        float v = rowacc[tid] + __ldg(&b2[h]);
        out[(size_t)(m0 + tid) * NH + h] = lrelu(v);
    }
}

// ---------------------------------------------------------------------------
extern "C" void kernel_launch(void* const* d_in, const int* in_sizes, int n_in,
                              void* d_out, int out_size) {
    const float* x  = (const float*)d_in[0];   // [2048, 512]
    const float* W1 = (const float*)d_in[1];   // [64, 512, 2048]
    const float* b1 = (const float*)d_in[2];   // [64, 2048]
    const float* W2 = (const float*)d_in[3];   // [64, 2048]
    const float* b2 = (const float*)d_in[4];   // [64]
    float* out = (float*)d_out;                // [2048, 64]
    (void)in_sizes; (void)n_in; (void)out_size;

    cudaFuncSetAttribute(mhmlp_main_kernel,
                         cudaFuncAttributeMaxDynamicSharedMemorySize, SMEM_DYN);

    {
        size_t n4 = (size_t)NH * ND * NHID / 4;
        convert_w_kernel<<<(int)((n4 + 255) / 256), 256>>>(W1);
    }
    {
        size_t n4 = (size_t)NB * ND / 4;
        convert_x_kernel<<<(int)((n4 + 255) / 256), 256>>>(x);
    }
    {
        int n = NH * (NHID / 2);
        pack_kernel<<<(n + 255) / 256, 256>>>(b1, W2);
    }

    dim3 grid(NB / BM, NH);
    mhmlp_main_kernel<<<grid, NTHREADS, SMEM_DYN>>>(b2, out);
}